// round 10
// baseline (speedup 1.0000x reference)
#include <cuda_runtime.h>
#include <cuda_bf16.h>

#define Gg 64
#define Nn 2048
#define Ee 16384
#define Ff 128
#define GE (Gg*Ee)          // 1048576 edges total
#define NL (Nn-1)           // 2047 non-center nodes per graph

// ---------------- scratch (static __device__ — no allocs allowed) ----------
__device__ int   g_is64;
__device__ int   g_deg[Gg*Nn];            // in-degree per global node
__device__ int   g_ccnt[Gg];              // # edges into center per graph
__device__ int   g_clist[Gg*128];         // edge ids into center (cap 128)
__device__ float g_A[Gg*Ff];              // ce@Wm_top + bm per graph
__device__ int   g_cnt[Nn];               // per-dst_local edge counts
__device__ int   g_off[Nn+1];             // CSR offsets
__device__ int   g_cur[Nn];               // scatter cursors
__device__ int   g_esrc[GE];              // CSR payload: src global id
__device__ float g_ecoef[GE];             // CSR payload: dis[src]*dis[dst]
__device__ float g_y[(size_t)Gg*Nn*Ff];   // mask*x  (67 MB)
__device__ float g_Zc[NL*Ff];             // mean_g aggregated y
__device__ float g_Zx[NL*Ff];             // mean_g aggregated x

__device__ __forceinline__ int ld_idx(const void* p, int is64, long long i) {
    return is64 ? (int)((const long long*)p)[i] : ((const int*)p)[i];
}

// ---------------- int32/int64 detection ------------------------------------
__global__ void k_detect(const unsigned int* w) {
    __shared__ int any;
    if (threadIdx.x == 0) any = 0;
    __syncthreads();
    int loc = 0;
    for (int i = threadIdx.x; i < 4096; i += blockDim.x) loc |= w[2*i + 1];
    if (loc) atomicOr(&any, 1);
    __syncthreads();
    if (threadIdx.x == 0) g_is64 = (any == 0) ? 1 : 0;
}

// ---------------- fused: in-degree + center-edge find + dst_local histogram --
__global__ void k_prep(const void* ei, const void* centers) {
    __shared__ int h[Nn];
    for (int i = threadIdx.x; i < Nn; i += blockDim.x) h[i] = 0;
    __syncthreads();
    int is64 = g_is64;
    for (int i = blockIdx.x * blockDim.x + threadIdx.x; i < GE;
         i += gridDim.x * blockDim.x) {
        int d = ld_idx(ei, is64, (long long)GE + i);
        atomicAdd(&g_deg[d], 1);
        atomicAdd(&h[d & (Nn - 1)], 1);
        int g = d >> 11;                     // d / Nn, Nn = 2048
        int c = ld_idx(centers, is64, g);
        if ((d & (Nn - 1)) == c) {
            int p = atomicAdd(&g_ccnt[g], 1);
            if (p < 128) g_clist[g*128 + p] = i;
        }
    }
    __syncthreads();
    for (int i = threadIdx.x; i < Nn; i += blockDim.x)
        if (h[i]) atomicAdd(&g_cnt[i], h[i]);
}

// ---------------- ce = h1[center],  A = ce@Wm_top + bm ----------------------
__global__ void k_ceA(const void* ei, const void* centers,
                      const float* __restrict__ x,
                      const float* __restrict__ W1, const float* __restrict__ b1,
                      const float* __restrict__ Wm, const float* __restrict__ bm) {
    int g = blockIdx.x, t = threadIdx.x;
    int is64 = g_is64;
    __shared__ int list[128];
    __shared__ int nsh;
    __shared__ float cex[Ff], ce[Ff];
    if (t == 0) nsh = min(g_ccnt[g], 128);
    __syncthreads();
    int n = nsh;
    if (t < n) list[t] = g_clist[g*128 + t];
    __syncthreads();
    if (t == 0) {  // sort by edge id -> deterministic accumulation order
        for (int a = 1; a < n; a++) {
            int v = list[a]; int b = a - 1;
            while (b >= 0 && list[b] > v) { list[b+1] = list[b]; b--; }
            list[b+1] = v;
        }
    }
    __syncthreads();
    int cidx = ld_idx(centers, is64, g);
    int cg = g * Nn + cidx;
    float degc = (float)(1 + g_deg[cg]);
    float disC = rsqrtf(degc);
    float acc = 0.f;
    for (int k = 0; k < n; k++) {
        int e = list[k];
        int s = ld_idx(ei, is64, (long long)e);
        float coef = rsqrtf((float)(1 + g_deg[s])) * disC;
        acc += x[(size_t)s*Ff + t] * coef;
    }
    acc += x[(size_t)cg*Ff + t] / degc;          // self term
    cex[t] = acc;
    __syncthreads();
    // 4-way split accumulators to break the serial FMA chain (latency-bound)
    {
        float s0 = 0.f, s1 = 0.f, s2 = 0.f, s3 = 0.f;
        #pragma unroll 8
        for (int f = 0; f < Ff; f += 4) {
            s0 += cex[f+0] * W1[(f+0)*Ff + t];
            s1 += cex[f+1] * W1[(f+1)*Ff + t];
            s2 += cex[f+2] * W1[(f+2)*Ff + t];
            s3 += cex[f+3] * W1[(f+3)*Ff + t];
        }
        ce[t] = b1[t] + ((s0 + s1) + (s2 + s3));
    }
    __syncthreads();
    {
        float s0 = 0.f, s1 = 0.f, s2 = 0.f, s3 = 0.f;
        #pragma unroll 8
        for (int h = 0; h < Ff; h += 4) {
            s0 += ce[h+0] * Wm[(h+0)*Ff + t];
            s1 += ce[h+1] * Wm[(h+1)*Ff + t];
            s2 += ce[h+2] * Wm[(h+2)*Ff + t];
            s3 += ce[h+3] * Wm[(h+3)*Ff + t];
        }
        g_A[g*Ff + t] = bm[t] + ((s0 + s1) + (s2 + s3));
    }
}

// ---------------- mask & y = mask*x  (register-tiled f32x2 GEMM) ------------
// 131008 x 128 x 128. Block: 128 threads, tile 128 rows x 128 cols.
// Thread tile: 8 rows x 16 cols (8 col-PAIRS, packed via fma.rn.f32x2).
// W col-pairs come straight from row-major smem; X rows staged duplicated
// (x,x) so both FFMA2 operands load as LDS.128 with no packing instructions.
#define MK_BM 128
__global__ void __launch_bounds__(128, 2)
k_masky(const float* __restrict__ x, const float* __restrict__ Wb) {
    extern __shared__ float sm[];
    float*  Ws = sm;                       // 128x128 = 64 KB
    float2* Xd = (float2*)(sm + 16384);    // [32 k][128 rows] dup pairs = 32 KB
    int t  = threadIdx.x;
    int tr = t >> 3;          // 0..15  -> rows tr*8 .. tr*8+7
    int tc = t & 7;           // 0..7   -> cols tc*16 .. tc*16+15

    for (int i = t; i < 4096; i += 128)
        ((float4*)Ws)[i] = ((const float4*)Wb)[i];

    const int total = Gg * NL;             // 131008
    int r0 = blockIdx.x * MK_BM;

    // staging: thread t owns row (r0 + t)
    int  rg_s = r0 + t;
    bool val_s = rg_s < total;
    int  g_s = rg_s / NL;
    int  v_s = rg_s - g_s * NL;
    size_t grow_s = (size_t)(g_s * Nn + v_s) * Ff;

    unsigned long long acc[8][8];
    #pragma unroll
    for (int r = 0; r < 8; r++)
        #pragma unroll
        for (int c = 0; c < 8; c++) acc[r][c] = 0ull;

    for (int kc = 0; kc < 4; kc++) {
        __syncthreads();                   // W ready (1st iter) / prev chunk done
        if (val_s) {
            #pragma unroll
            for (int i = 0; i < 8; i++) {
                float4 xv = ((const float4*)(x + grow_s + kc*32))[i];
                int k0 = i * 4;
                Xd[(k0+0)*128 + t] = make_float2(xv.x, xv.x);
                Xd[(k0+1)*128 + t] = make_float2(xv.y, xv.y);
                Xd[(k0+2)*128 + t] = make_float2(xv.z, xv.z);
                Xd[(k0+3)*128 + t] = make_float2(xv.w, xv.w);
            }
        } else {
            float2 z = make_float2(0.f, 0.f);
            #pragma unroll
            for (int k0 = 0; k0 < 32; k0++) Xd[k0*128 + t] = z;
        }
        __syncthreads();

        #pragma unroll 4
        for (int k = 0; k < 32; k++) {
            unsigned long long xd[8], wp[8];
            const ulonglong2* xp = (const ulonglong2*)(Xd + k*128 + tr*8);
            #pragma unroll
            for (int i = 0; i < 4; i++) { ulonglong2 v = xp[i]; xd[2*i] = v.x; xd[2*i+1] = v.y; }
            // NOTE: W row is the GLOBAL k = kc*32 + k (R6 bug: used local k)
            const ulonglong2* wq = (const ulonglong2*)(Ws + (kc*32 + k)*128 + tc*16);
            #pragma unroll
            for (int i = 0; i < 4; i++) { ulonglong2 v = wq[i]; wp[2*i] = v.x; wp[2*i+1] = v.y; }
            #pragma unroll
            for (int r = 0; r < 8; r++)
                #pragma unroll
                for (int c = 0; c < 8; c++)
                    asm("fma.rn.f32x2 %0, %1, %2, %0;"
                        : "+l"(acc[r][c]) : "l"(xd[r]), "l"(wp[c]));
        }
    }

    // epilogue: mask = relu(A_g + acc), y = mask * x  (x re-read: L2-hot)
    #pragma unroll
    for (int r = 0; r < 8; r++) {
        int rg = r0 + tr*8 + r;
        if (rg < total) {
            int g = rg / NL;
            int v = rg - g * NL;
            size_t grow = (size_t)(g * Nn + v) * Ff;
            const float2* Arow = (const float2*)(g_A + g*Ff);
            const float2* xrow = (const float2*)(x + grow);
            float2*       yrow = (float2*)(g_y + grow);
            #pragma unroll
            for (int c = 0; c < 8; c++) {
                int cp = tc*8 + c;                     // cols 2cp, 2cp+1
                float2 s = *(float2*)&acc[r][c];
                float2 a2 = Arow[cp];
                float2 xv = xrow[cp];
                float m0 = fmaxf(a2.x + s.x, 0.f);
                float m1 = fmaxf(a2.y + s.y, 0.f);
                yrow[cp] = make_float2(m0 * xv.x, m1 * xv.y);
            }
        }
    }
}

// ---------------- CSR build: scan / scatter ---------------------------------
__global__ void k_scan() {
    __shared__ int a[Nn], b[Nn];
    int t = threadIdx.x;
    a[t] = g_cnt[t]; a[t + 1024] = g_cnt[t + 1024];
    __syncthreads();
    int* src = a; int* dst = b;
    for (int off = 1; off < Nn; off <<= 1) {
        for (int i = t; i < Nn; i += 1024) {
            int v = src[i];
            if (i >= off) v += src[i - off];
            dst[i] = v;
        }
        __syncthreads();
        int* tmp = src; src = dst; dst = tmp;
    }
    for (int i = t; i < Nn; i += 1024) {
        int excl = i ? src[i-1] : 0;
        g_off[i] = excl;
        g_cur[i] = excl;
    }
    if (t == 0) g_off[Nn] = src[Nn-1];
}

__global__ void k_scatter(const void* ei) {
    int is64 = g_is64;
    int i = blockIdx.x * blockDim.x + threadIdx.x;
    if (i >= GE) return;
    int s = ld_idx(ei, is64, (long long)i);
    int d = ld_idx(ei, is64, (long long)GE + i);
    int dl = d & (Nn - 1);
    int pos = atomicAdd(&g_cur[dl], 1);
    g_esrc[pos] = s;
    g_ecoef[pos] = rsqrtf((float)(1 + g_deg[s])) * rsqrtf((float)(1 + g_deg[d]));
}

// ---------------- pull aggregation: Zc, Zx ----------------------------------
__global__ void k_pull(const float* __restrict__ x) {
    int d = blockIdx.x, t = threadIdx.x;
    __shared__ int   ss[128];
    __shared__ float sc[128];
    float ac = 0.f, ax = 0.f;
    int beg = g_off[d], end = g_off[d+1];
    for (int j0 = beg; j0 < end; j0 += 128) {
        int n = min(128, end - j0);
        if (t < n) { ss[t] = g_esrc[j0 + t]; sc[t] = g_ecoef[j0 + t]; }
        __syncthreads();
        #pragma unroll 4
        for (int j = 0; j < n; j++) {
            int s = ss[j]; float c = sc[j];
            size_t base = (size_t)s*Ff + t;
            ac += g_y[base] * c;
            ax += __ldg(&x[base]) * c;
        }
        __syncthreads();
    }
    #pragma unroll 4
    for (int g = 0; g < Gg; g++) {           // self terms, all graphs
        int row = g * Nn + d;
        float invd = 1.0f / (float)(1 + g_deg[row]);
        size_t base = (size_t)row*Ff + t;
        ac += g_y[base] * invd;
        ax += __ldg(&x[base]) * invd;
    }
    const float inv = 1.0f / (float)Gg;
    g_Zc[d*Ff + t] = ac * inv;
    g_Zx[d*Ff + t] = ax * inv;
}

// ---------------- output GEMMs: core = Zc@W2+b2, red = (Zx-Zc)@W3+b3 --------
__global__ void k_out(const float* __restrict__ W2, const float* __restrict__ b2,
                      const float* __restrict__ W3, const float* __restrict__ b3,
                      float* __restrict__ out) {
    int t = threadIdx.x;
    int d0 = blockIdx.x * 16;
    int nr = min(16, NL - d0);
    __shared__ float zc[16][128], zr[16][128];
    for (int r = 0; r < nr; r++) {
        float c = g_Zc[(d0 + r)*128 + t];
        zc[r][t] = c;
        zr[r][t] = g_Zx[(d0 + r)*128 + t] - c;
    }
    __syncthreads();
    float a[16], b[16];
    #pragma unroll
    for (int r = 0; r < 16; r++) { a[r] = b2[t]; b[r] = b3[t]; }
    for (int k = 0; k < 128; k++) {
        float w2 = W2[k*128 + t], w3 = W3[k*128 + t];
        #pragma unroll
        for (int r = 0; r < 16; r++) {
            a[r] += zc[r][k] * w2;
            b[r] += zr[r][k] * w3;
        }
    }
    for (int r = 0; r < nr; r++) {
        out[(size_t)(d0 + r)*128 + t] = a[r];
        out[(size_t)NL*128 + (size_t)(d0 + r)*128 + t] = b[r];
    }
}

// ---------------- launch -----------------------------------------------------
extern "C" void kernel_launch(void* const* d_in, const int* in_sizes, int n_in,
                              void* d_out, int out_size) {
    const float* x       = (const float*)d_in[0];
    const void*  ei      = d_in[1];
    const void*  centers = d_in[3];
    const float* W1 = (const float*)d_in[4];
    const float* b1 = (const float*)d_in[5];
    const float* W2 = (const float*)d_in[6];
    const float* b2 = (const float*)d_in[7];
    const float* W3 = (const float*)d_in[8];
    const float* b3 = (const float*)d_in[9];
    const float* Wm = (const float*)d_in[10];
    const float* bm = (const float*)d_in[11];
    float* out = (float*)d_out;

    void *p_deg, *p_ccnt, *p_cnt;
    cudaGetSymbolAddress(&p_deg,  g_deg);
    cudaGetSymbolAddress(&p_ccnt, g_ccnt);
    cudaGetSymbolAddress(&p_cnt,  g_cnt);
    cudaMemsetAsync(p_deg,  0, sizeof(int)*Gg*Nn);
    cudaMemsetAsync(p_ccnt, 0, sizeof(int)*Gg);
    cudaMemsetAsync(p_cnt,  0, sizeof(int)*Nn);

    k_detect<<<1, 256>>>((const unsigned int*)ei);
    k_prep<<<512, 256>>>(ei, centers);
    k_ceA<<<Gg, 128>>>(ei, centers, x, W1, b1, Wm, bm);

    int smem = (16384 + 32*128*2) * 4;   // 96 KB: Ws + Xd
    cudaFuncSetAttribute(k_masky, cudaFuncAttributeMaxDynamicSharedMemorySize, smem);
    int ntiles = (Gg*NL + MK_BM - 1) / MK_BM;   // 1024
    k_masky<<<ntiles, 128, smem>>>(x, Wm + Ff*Ff);   // bottom half of Wm

    k_scan<<<1, 1024>>>();
    k_scatter<<<GE/256, 256>>>(ei);
    k_pull<<<NL, 128>>>(x);
    k_out<<<(NL + 15)/16, 128>>>(W2, b2, W3, b3, out);
}